// round 14
// baseline (speedup 1.0000x reference)
#include <cuda_runtime.h>

#define BB 512
#define TT 512
#define FF 64
#define HH 128
#define GG 512   // 4*H
#define BT (BB*TT)
#define C_OUT 10

typedef unsigned long long u64;

// ---------- packed f32x2 helpers (Blackwell FFMA2 path) ----------
__device__ __forceinline__ u64 pack2(float x, float y) {
    u64 r; asm("mov.b64 %0, {%1,%2};" : "=l"(r) : "f"(x), "f"(y)); return r;
}
__device__ __forceinline__ u64 ffma2(u64 a, u64 b, u64 c) {
    u64 d; asm("fma.rn.f32x2 %0, %1, %2, %3;" : "=l"(d) : "l"(a), "l"(b), "l"(c)); return d;
}
__device__ __forceinline__ u64 fadd2(u64 a, u64 b) {
    u64 d; asm("add.rn.f32x2 %0, %1, %2;" : "=l"(d) : "l"(a), "l"(b)); return d;
}
__device__ __forceinline__ float hadd2(u64 a) {
    float lo, hi; asm("mov.b64 {%0,%1}, %2;" : "=f"(lo), "=f"(hi) : "l"(a));
    return lo + hi;
}

__device__ __forceinline__ float sigm(float z) {
    return __fdividef(1.f, 1.f + __expf(-z));
}
__device__ __forceinline__ float tanh_f(float z) {
    return 1.f - __fdividef(2.f, __expf(2.f * z) + 1.f);
}

// ---------- scratch (device globals; no allocation allowed) ----------
__device__ __align__(16) float g_xp[(long)BT * GG];   // 512 MB, reused both layers
__device__ __align__(16) float g_h1[(long)BT * HH];   // 128 MB, layer-1 outputs
__device__ __align__(16) float g_last[BB * HH];
__device__ __align__(16) float g_wt5[2][65536];       // unit-major packed W_hh
__device__ __align__(16) float g_bias[2][GG];

// ---------- prep: pack W_hh unit-major ----------
// For thread (j = tid>>1, kh = tid&1), chunk c in [0,32): global k2 = 32*kh + c.
// Entry at ulonglong2 index (c*256 + tid)*2:
//   IF = { (Wi[2K2],Wi[2K2+1]), (Wf[2K2],Wf[2K2+1]) }   rows j, 128+j
//   GO = { (Wg...), (Wo...) }                           rows 256+j, 384+j
__global__ void prep5(const float* __restrict__ w1hh, const float* __restrict__ w2hh,
                      const float* __restrict__ b1i, const float* __restrict__ b1h,
                      const float* __restrict__ b2i, const float* __restrict__ b2h) {
    int layer = blockIdx.y;
    const float* w = layer ? w2hh : w1hh;
    int gid = blockIdx.x * blockDim.x + threadIdx.x;  // [0, 8192)
    int c = gid >> 8;
    int tid = gid & 255;
    int j = tid >> 1, kh = tid & 1;
    int k = 2 * (32 * kh + c);
    ulonglong2* o = (ulonglong2*)g_wt5[layer] + (size_t)(c * 256 + tid) * 2;
    ulonglong2 IF, GO;
    IF.x = pack2(w[j * HH + k],         w[j * HH + k + 1]);
    IF.y = pack2(w[(128 + j) * HH + k], w[(128 + j) * HH + k + 1]);
    GO.x = pack2(w[(256 + j) * HH + k], w[(256 + j) * HH + k + 1]);
    GO.y = pack2(w[(384 + j) * HH + k], w[(384 + j) * HH + k + 1]);
    o[0] = IF;
    o[1] = GO;
    if (gid < GG) {
        g_bias[layer][gid] = layer ? (b2i[gid] + b2h[gid]) : (b1i[gid] + b1h[gid]);
    }
}

// ---------- x-projection GEMM: double-buffered, BK=16, one barrier/tile ----------
#define GBM 128
#define GBN 128
#define DBK 16

__global__ void __launch_bounds__(256, 2) gemm_db(
        const float* __restrict__ in_, const float* __restrict__ wih,
        const float* __restrict__ bias, float* __restrict__ out, int K) {
    __shared__ __align__(16) float A_s[2][DBK][GBM + 4];
    __shared__ __align__(16) u64   B_s[2][DBK][GBN / 2 + 2];

    int tid = threadIdx.x;
    int tx = tid & 15;
    int ty = tid >> 4;
    long m0 = (long)blockIdx.x * GBM;
    int n0 = blockIdx.y * GBN;

    u64 acc[8][4];
#pragma unroll
    for (int i = 0; i < 8; i++)
#pragma unroll
        for (int j = 0; j < 4; j++) acc[i][j] = 0ull;

    int a_lk = (tid & 3) * 4;
    int a_lm = tid >> 2;
    int b_p  = tid >> 2;
    int b_q  = (tid & 3) * 4;

    const int nt = K / DBK;

    {
        float4 v0 = *(const float4*)&in_[(m0 + a_lm) * K + a_lk];
        float4 v1 = *(const float4*)&in_[(m0 + a_lm + 64) * K + a_lk];
        int g = n0 + 2 * b_p;
        float4 x = *(const float4*)&wih[(long)g * K + b_q];
        float4 y = *(const float4*)&wih[(long)(g + 1) * K + b_q];
        A_s[0][a_lk + 0][a_lm] = v0.x;
        A_s[0][a_lk + 1][a_lm] = v0.y;
        A_s[0][a_lk + 2][a_lm] = v0.z;
        A_s[0][a_lk + 3][a_lm] = v0.w;
        A_s[0][a_lk + 0][a_lm + 64] = v1.x;
        A_s[0][a_lk + 1][a_lm + 64] = v1.y;
        A_s[0][a_lk + 2][a_lm + 64] = v1.z;
        A_s[0][a_lk + 3][a_lm + 64] = v1.w;
        B_s[0][b_q + 0][b_p] = pack2(x.x, y.x);
        B_s[0][b_q + 1][b_p] = pack2(x.y, y.y);
        B_s[0][b_q + 2][b_p] = pack2(x.z, y.z);
        B_s[0][b_q + 3][b_p] = pack2(x.w, y.w);
    }
    __syncthreads();

    for (int it = 0; it < nt; it++) {
        int buf = it & 1;
        float4 v0, v1, x, y;
        bool have_next = (it + 1 < nt);
        if (have_next) {
            int kt = (it + 1) * DBK;
            v0 = *(const float4*)&in_[(m0 + a_lm) * K + kt + a_lk];
            v1 = *(const float4*)&in_[(m0 + a_lm + 64) * K + kt + a_lk];
            int g = n0 + 2 * b_p;
            x = *(const float4*)&wih[(long)g * K + kt + b_q];
            y = *(const float4*)&wih[(long)(g + 1) * K + kt + b_q];
        }

#pragma unroll
        for (int kk = 0; kk < DBK; kk++) {
            float4 a0 = *(const float4*)&A_s[buf][kk][ty * 4];
            float4 a1 = *(const float4*)&A_s[buf][kk][64 + ty * 4];
            ulonglong2 bA = *(const ulonglong2*)&B_s[buf][kk][2 * tx];
            ulonglong2 bB = *(const ulonglong2*)&B_s[buf][kk][32 + 2 * tx];
            u64 ad;
#define GEMM_ROW(r, av) \
            ad = pack2(av, av); \
            acc[r][0] = ffma2(ad, bA.x, acc[r][0]); \
            acc[r][1] = ffma2(ad, bA.y, acc[r][1]); \
            acc[r][2] = ffma2(ad, bB.x, acc[r][2]); \
            acc[r][3] = ffma2(ad, bB.y, acc[r][3]);
            GEMM_ROW(0, a0.x)
            GEMM_ROW(1, a0.y)
            GEMM_ROW(2, a0.z)
            GEMM_ROW(3, a0.w)
            GEMM_ROW(4, a1.x)
            GEMM_ROW(5, a1.y)
            GEMM_ROW(6, a1.z)
            GEMM_ROW(7, a1.w)
#undef GEMM_ROW
        }

        if (have_next) {
            int nb = buf ^ 1;
            A_s[nb][a_lk + 0][a_lm] = v0.x;
            A_s[nb][a_lk + 1][a_lm] = v0.y;
            A_s[nb][a_lk + 2][a_lm] = v0.z;
            A_s[nb][a_lk + 3][a_lm] = v0.w;
            A_s[nb][a_lk + 0][a_lm + 64] = v1.x;
            A_s[nb][a_lk + 1][a_lm + 64] = v1.y;
            A_s[nb][a_lk + 2][a_lm + 64] = v1.z;
            A_s[nb][a_lk + 3][a_lm + 64] = v1.w;
            B_s[nb][b_q + 0][b_p] = pack2(x.x, y.x);
            B_s[nb][b_q + 1][b_p] = pack2(x.y, y.y);
            B_s[nb][b_q + 2][b_p] = pack2(x.z, y.z);
            B_s[nb][b_q + 3][b_p] = pack2(x.w, y.w);
        }
        __syncthreads();
    }

    const u64* bias64 = (const u64*)bias;
    u64 bv0 = bias64[n0 / 2 + 2 * tx];
    u64 bv1 = bias64[n0 / 2 + 2 * tx + 1];
    u64 bv2 = bias64[n0 / 2 + 32 + 2 * tx];
    u64 bv3 = bias64[n0 / 2 + 32 + 2 * tx + 1];
#pragma unroll
    for (int r = 0; r < 8; r++) {
        int m = (r < 4) ? (ty * 4 + r) : (64 + ty * 4 + (r - 4));
        u64* orow = (u64*)(out + (m0 + m) * GG);
        ulonglong2 s0, s1;
        s0.x = fadd2(acc[r][0], bv0); s0.y = fadd2(acc[r][1], bv1);
        s1.x = fadd2(acc[r][2], bv2); s1.y = fadd2(acc[r][3], bv3);
        *(ulonglong2*)&orow[n0 / 2 + 2 * tx] = s0;
        *(ulonglong2*)&orow[n0 / 2 + 32 + 2 * tx] = s1;
    }
}

// ---------- LSTM recurrence v7: unit-major, shfl-combine, 1 barrier/step ----------
// Thread (j = tid>>1, kh = tid&1): all 4 gates of unit j, 4 batches, k-half kh.
// Partial gate sums exchanged with adjacent lane via shfl_xor(1); state update
// in-thread for owned batches {2kh, 2kh+1}. h double-buffered in smem.
#define WR 16                          // k2-chunks (of 32) held in registers
#define WS (32 - WR)                   // k2-chunks in smem
#define L7_W_BYTES (WS * 512 * 16)     // [WS][IF x256 | GO x256] ulonglong2
#define L7_SMEM (L7_W_BYTES + 2 * 4 * HH * 4)

__global__ void __launch_bounds__(256, 1) lstm_rec7(
        const float* __restrict__ xp, const float* __restrict__ wt5,
        float* __restrict__ out, int write_all) {
    extern __shared__ __align__(16) char smem_raw[];
    ulonglong2* wsm = (ulonglong2*)smem_raw;
    float (*hs)[4][HH] = (float(*)[4][HH])(smem_raw + L7_W_BYTES);  // [2][4][128]

    int tid = threadIdx.x;
    const int j = tid >> 1;
    const int kh = tid & 1;
    int b0 = blockIdx.x * 4;

    const ulonglong2* wp = (const ulonglong2*)wt5;

    // W registers: chunks c in [0, WR)
    u64 wi[WR], wf[WR], wg[WR], wo[WR];
#pragma unroll
    for (int c = 0; c < WR; c++) {
        ulonglong2 IF = wp[(size_t)(c * 256 + tid) * 2];
        ulonglong2 GO = wp[(size_t)(c * 256 + tid) * 2 + 1];
        wi[c] = IF.x; wf[c] = IF.y; wg[c] = GO.x; wo[c] = GO.y;
    }
    // W smem: chunks c in [WR, 32) -> row (c-WR): [IF at tid | GO at 256+tid]
    for (int c = 0; c < WS; c++) {
        ulonglong2 IF = wp[(size_t)((WR + c) * 256 + tid) * 2];
        ulonglong2 GO = wp[(size_t)((WR + c) * 256 + tid) * 2 + 1];
        wsm[c * 512 + tid] = IF;
        wsm[c * 512 + 256 + tid] = GO;
    }

    // init h buffers = 0
    for (int i = tid; i < 2 * 4 * HH; i += 256) ((float*)hs)[i] = 0.f;
    float c_reg[2] = {0.f, 0.f};
    __syncthreads();

    const int ob = 2 * kh;       // owned batch base
    const int hb = 64 * kh;      // k-range start in h

    for (int ts = 0; ts < TT; ts++) {
        float (*hc)[HH] = hs[ts & 1];
        float (*hn)[HH] = hs[(ts & 1) ^ 1];

        // xp for owned batches (independent of h; issued before dot loop)
        const float* xpp0 = xp + ((long)(b0 + ob) * TT + ts) * GG;
        const float* xpp1 = xp + ((long)(b0 + ob + 1) * TT + ts) * GG;
        float xq00 = xpp0[j], xq01 = xpp0[HH + j], xq02 = xpp0[2 * HH + j], xq03 = xpp0[3 * HH + j];
        float xq10 = xpp1[j], xq11 = xpp1[HH + j], xq12 = xpp1[2 * HH + j], xq13 = xpp1[3 * HH + j];

        u64 ai0 = 0, ai1 = 0, ai2 = 0, ai3 = 0;
        u64 af0 = 0, af1 = 0, af2 = 0, af3 = 0;
        u64 ag0 = 0, ag1 = 0, ag2 = 0, ag3 = 0;
        u64 ao0 = 0, ao1 = 0, ao2 = 0, ao3 = 0;

#define DOT4(I0, I1, F0, F1, G0, G1, O0, O1, HOFF) \
        { \
            ulonglong2 h0 = *(const ulonglong2*)&hc[0][HOFF]; \
            ulonglong2 h1 = *(const ulonglong2*)&hc[1][HOFF]; \
            ulonglong2 h2 = *(const ulonglong2*)&hc[2][HOFF]; \
            ulonglong2 h3 = *(const ulonglong2*)&hc[3][HOFF]; \
            ai0 = ffma2(I0, h0.x, ai0); ai0 = ffma2(I1, h0.y, ai0); \
            af0 = ffma2(F0, h0.x, af0); af0 = ffma2(F1, h0.y, af0); \
            ag0 = ffma2(G0, h0.x, ag0); ag0 = ffma2(G1, h0.y, ag0); \
            ao0 = ffma2(O0, h0.x, ao0); ao0 = ffma2(O1, h0.y, ao0); \
            ai1 = ffma2(I0, h1.x, ai1); ai1 = ffma2(I1, h1.y, ai1); \
            af1 = ffma2(F0, h1.x, af1); af1 = ffma2(F1, h1.y, af1); \
            ag1 = ffma2(G0, h1.x, ag1); ag1 = ffma2(G1, h1.y, ag1); \
            ao1 = ffma2(O0, h1.x, ao1); ao1 = ffma2(O1, h1.y, ao1); \
            ai2 = ffma2(I0, h2.x, ai2); ai2 = ffma2(I1, h2.y, ai2); \
            af2 = ffma2(F0, h2.x, af2); af2 = ffma2(F1, h2.y, af2); \
            ag2 = ffma2(G0, h2.x, ag2); ag2 = ffma2(G1, h2.y, ag2); \
            ao2 = ffma2(O0, h2.x, ao2); ao2 = ffma2(O1, h2.y, ao2); \
            ai3 = ffma2(I0, h3.x, ai3); ai3 = ffma2(I1, h3.y, ai3); \
            af3 = ffma2(F0, h3.x, af3); af3 = ffma2(F1, h3.y, af3); \
            ag3 = ffma2(G0, h3.x, ag3); ag3 = ffma2(G1, h3.y, ag3); \
            ao3 = ffma2(O0, h3.x, ao3); ao3 = ffma2(O1, h3.y, ao3); \
        }

        // register part: local k in [0, 2*WR)
#pragma unroll
        for (int cc = 0; cc < WR / 2; cc++) {
            DOT4(wi[2 * cc], wi[2 * cc + 1], wf[2 * cc], wf[2 * cc + 1],
                 wg[2 * cc], wg[2 * cc + 1], wo[2 * cc], wo[2 * cc + 1],
                 hb + 4 * cc)
        }
        // smem part: local k in [2*WR, 64)
#pragma unroll
        for (int cc = 0; cc < WS / 2; cc++) {
            ulonglong2 IF0 = wsm[(2 * cc) * 512 + tid];
            ulonglong2 GO0 = wsm[(2 * cc) * 512 + 256 + tid];
            ulonglong2 IF1 = wsm[(2 * cc + 1) * 512 + tid];
            ulonglong2 GO1 = wsm[(2 * cc + 1) * 512 + 256 + tid];
            DOT4(IF0.x, IF1.x, IF0.y, IF1.y, GO0.x, GO1.x, GO0.y, GO1.y,
                 hb + 2 * WR + 4 * cc)
        }
#undef DOT4

        // horizontal partials p[gate][batch]
        float pi0 = hadd2(ai0), pi1 = hadd2(ai1), pi2 = hadd2(ai2), pi3 = hadd2(ai3);
        float pf0 = hadd2(af0), pf1 = hadd2(af1), pf2 = hadd2(af2), pf3 = hadd2(af3);
        float pg0 = hadd2(ag0), pg1 = hadd2(ag1), pg2 = hadd2(ag2), pg3 = hadd2(ag3);
        float po0 = hadd2(ao0), po1 = hadd2(ao1), po2 = hadd2(ao2), po3 = hadd2(ao3);

        // exchange with k-half partner (adjacent lane): send non-owned batches
        float si0 = kh ? pi0 : pi2, si1 = kh ? pi1 : pi3;
        float sf0 = kh ? pf0 : pf2, sf1 = kh ? pf1 : pf3;
        float sg0 = kh ? pg0 : pg2, sg1 = kh ? pg1 : pg3;
        float so0 = kh ? po0 : po2, so1 = kh ? po1 : po3;
        float ri0 = __shfl_xor_sync(0xffffffffu, si0, 1);
        float ri1 = __shfl_xor_sync(0xffffffffu, si1, 1);
        float rf0 = __shfl_xor_sync(0xffffffffu, sf0, 1);
        float rf1 = __shfl_xor_sync(0xffffffffu, sf1, 1);
        float rg0 = __shfl_xor_sync(0xffffffffu, sg0, 1);
        float rg1 = __shfl_xor_sync(0xffffffffu, sg1, 1);
        float ro0 = __shfl_xor_sync(0xffffffffu, so0, 1);
        float ro1 = __shfl_xor_sync(0xffffffffu, so1, 1);

        float zi0 = (kh ? pi2 : pi0) + ri0 + xq00;
        float zf0 = (kh ? pf2 : pf0) + rf0 + xq01;
        float zg0 = (kh ? pg2 : pg0) + rg0 + xq02;
        float zo0 = (kh ? po2 : po0) + ro0 + xq03;
        float zi1 = (kh ? pi3 : pi1) + ri1 + xq10;
        float zf1 = (kh ? pf3 : pf1) + rf1 + xq11;
        float zg1 = (kh ? pg3 : pg1) + rg1 + xq12;
        float zo1 = (kh ? po3 : po1) + ro1 + xq13;

        // state update, owned batches ob, ob+1
        {
            float iv = sigm(zi0), fv = sigm(zf0), gv = tanh_f(zg0), ov = sigm(zo0);
            float c = fv * c_reg[0] + iv * gv;
            c_reg[0] = c;
            float h = ov * tanh_f(c);
            hn[ob][j] = h;
            if (write_all) out[((long)(b0 + ob) * TT + ts) * HH + j] = h;
            else if (ts == TT - 1) out[(b0 + ob) * HH + j] = h;
        }
        {
            float iv = sigm(zi1), fv = sigm(zf1), gv = tanh_f(zg1), ov = sigm(zo1);
            float c = fv * c_reg[1] + iv * gv;
            c_reg[1] = c;
            float h = ov * tanh_f(c);
            hn[ob + 1][j] = h;
            if (write_all) out[((long)(b0 + ob + 1) * TT + ts) * HH + j] = h;
            else if (ts == TT - 1) out[(b0 + ob + 1) * HH + j] = h;
        }
        __syncthreads();
    }
}

// ---------- final FC + sigmoid: out[512][10] ----------
__global__ void fc_kernel(const float* __restrict__ last, const float* __restrict__ wfc,
                          const float* __restrict__ bfc, float* __restrict__ out) {
    int b = blockIdx.x;
    int lane = threadIdx.x;  // 32 threads
    float4 v = ((const float4*)(last + b * HH))[lane];
    for (int c = 0; c < C_OUT; c++) {
        float4 w = ((const float4*)(wfc + c * HH))[lane];
        float s = v.x * w.x + v.y * w.y + v.z * w.z + v.w * w.w;
#pragma unroll
        for (int off = 16; off; off >>= 1) s += __shfl_xor_sync(0xffffffffu, s, off);
        if (lane == 0) out[b * C_OUT + c] = sigm(s + bfc[c]);
    }
}

extern "C" void kernel_launch(void* const* d_in, const int* in_sizes, int n_in,
                              void* d_out, int out_size) {
    const float* x     = (const float*)d_in[0];
    const float* w1_ih = (const float*)d_in[1];
    const float* w1_hh = (const float*)d_in[2];
    const float* b1_ih = (const float*)d_in[3];
    const float* b1_hh = (const float*)d_in[4];
    const float* w2_ih = (const float*)d_in[5];
    const float* w2_hh = (const float*)d_in[6];
    const float* b2_ih = (const float*)d_in[7];
    const float* b2_hh = (const float*)d_in[8];
    const float* w_fc  = (const float*)d_in[9];
    const float* b_fc  = (const float*)d_in[10];
    float* out = (float*)d_out;

    float *xp, *h1, *last, *wt5, *bias;
    cudaGetSymbolAddress((void**)&xp,   g_xp);
    cudaGetSymbolAddress((void**)&h1,   g_h1);
    cudaGetSymbolAddress((void**)&last, g_last);
    cudaGetSymbolAddress((void**)&wt5,  g_wt5);
    cudaGetSymbolAddress((void**)&bias, g_bias);

    const float* wt5_1  = wt5;
    const float* wt5_2  = wt5 + 65536;
    const float* bias_1 = bias;
    const float* bias_2 = bias + GG;

    cudaFuncSetAttribute(lstm_rec7, cudaFuncAttributeMaxDynamicSharedMemorySize,
                         L7_SMEM);

    prep5<<<dim3(32, 2), 256>>>(w1_hh, w2_hh, b1_ih, b1_hh, b2_ih, b2_hh);

    // Layer 1
    gemm_db<<<dim3(BT / GBM, GG / GBN), 256>>>(x, w1_ih, bias_1, xp, FF);
    lstm_rec7<<<BB / 4, 256, L7_SMEM>>>(xp, wt5_1, h1, 1);

    // Layer 2
    gemm_db<<<dim3(BT / GBM, GG / GBN), 256>>>(h1, w2_ih, bias_2, xp, HH);
    lstm_rec7<<<BB / 4, 256, L7_SMEM>>>(xp, wt5_2, last, 0);

    // FC head
    fc_kernel<<<BB, 32>>>(last, w_fc, b_fc, out);
}